// round 1
// baseline (speedup 1.0000x reference)
#include <cuda_runtime.h>
#include <cstdint>

#define WV 14          // valid width
#define WP 16          // padded width in global buffers (col 0 and 15 are zero pad)
#define SP 20          // smem row pitch (floats) - breaks bank conflicts
#define B_TOTAL 2048

// Scratch: per-sample slab is 32768 floats for every intermediate layer:
// conv1 out: 64*32*16, conv2 out: 128*16*16, conv3 out: 256*8*16  (all = 32768)
__device__ float g_bufA[(size_t)B_TOTAL * 32768];
__device__ float g_bufB[(size_t)B_TOTAL * 32768];

// ---- packed f32x2 helpers (Blackwell sm_103a FFMA2 path) ----
__device__ __forceinline__ unsigned long long pack2(float x) {
    unsigned long long r;
    asm("mov.b64 %0, {%1, %1};" : "=l"(r) : "f"(x));
    return r;
}
__device__ __forceinline__ void fma2(unsigned long long &acc,
                                     unsigned long long a,
                                     unsigned long long b) {
    asm("fma.rn.f32x2 %0, %1, %2, %0;" : "+l"(acc) : "l"(a), "l"(b));
}
__device__ __forceinline__ float2 unpack2(unsigned long long v) {
    float2 r;
    asm("mov.b64 {%0, %1}, %2;" : "=f"(r.x), "=f"(r.y) : "l"(v));
    return r;
}

// =====================================================================
// Fused conv(3x3, stride (2,1), pad (1,1)) + BN(eval) + ReLU
// One CTA per batch sample. Input slab staged in SMEM (pitch SP).
// Thread (cp, h) computes 14 outputs for output channels {co, co+1}.
// Requires (CO_CHUNK/2) * HOUT == 256.
// =====================================================================
template<int CIN, int COUT, int HIN, int HOUT, int CO_CHUNK, int CI_BLK, bool FIRST>
__global__ void __launch_bounds__(256, 1)
conv_bn_relu_kernel(const float* __restrict__ in0,
                    const float* __restrict__ in1,   // sigmas when FIRST
                    const float* __restrict__ wgt,   // [COUT][CIN][3][3]
                    const float* __restrict__ gam,
                    const float* __restrict__ bet,
                    const float* __restrict__ mu,
                    const float* __restrict__ var,
                    float* __restrict__ out)         // [B][COUT][HOUT][WP]
{
    constexpr int IN_G    = CIN * HIN * WP;   // global input elems per sample
    constexpr int IN_SM   = CIN * HIN * SP;   // smem input elems
    constexpr int W_ELEMS = CI_BLK * 9 * CO_CHUNK;

    extern __shared__ float smem[];
    float* s_in = smem;                 // [CIN][HIN][SP]
    float* s_w  = smem + IN_SM;         // [CI_BLK][9][CO_CHUNK]

    const int b   = blockIdx.x;
    const int tid = threadIdx.x;

    if (FIRST) {
        // Build 2-channel input: ch0 = x, ch1 = 10*sigmas. Zero the pads.
        for (int r = tid; r < 2 * HIN; r += 256) {
            s_in[r * SP]          = 0.0f;
            s_in[r * SP + WV + 1] = 0.0f;
        }
        for (int i = tid; i < HIN * WV; i += 256) {
            int f = i / WV, k = i % WV;
            s_in[f * SP + 1 + k]            = in0[(size_t)b * (HIN * WV) + i];
            s_in[(HIN + f) * SP + 1 + k]    = in1[(size_t)b * (HIN * WV) + i] * 10.0f;
        }
    } else {
        const float* gin = in0 + (size_t)b * IN_G;
        for (int i = tid * 4; i < IN_G; i += 256 * 4) {
            float4 v = *reinterpret_cast<const float4*>(gin + i);
            int row = i >> 4;       // /WP
            int col = i & 15;
            *reinterpret_cast<float4*>(s_in + row * SP + col) = v;
        }
    }

    const int h  = tid % HOUT;
    const int cp = tid / HOUT;   // co-pair index within chunk

    for (int co0 = 0; co0 < COUT; co0 += CO_CHUNK) {
        unsigned long long acc[WV];
        #pragma unroll
        for (int w = 0; w < WV; w++) acc[w] = 0ull;

        for (int ci0 = 0; ci0 < CIN; ci0 += CI_BLK) {
            __syncthreads();   // protect s_w reuse + (first iter) s_in staging
            for (int e = tid; e < W_ELEMS; e += 256) {
                int co_l = e % CO_CHUNK;
                int rest = e / CO_CHUNK;
                int k    = rest % 9;
                int ci_l = rest / 9;
                s_w[e] = wgt[(size_t)(co0 + co_l) * (CIN * 9) + (ci0 + ci_l) * 9 + k];
            }
            __syncthreads();

            for (int ci = 0; ci < CI_BLK; ci++) {
                const float* w_base = s_w + (ci * 9) * CO_CHUNK + 2 * cp;
                const float* i_base = s_in + (ci0 + ci) * (HIN * SP);
                #pragma unroll
                for (int kh = 0; kh < 3; kh++) {
                    int r = 2 * h - 1 + kh;
                    if (r < 0) continue;            // only h==0, kh==0
                    const float4* row4 =
                        reinterpret_cast<const float4*>(i_base + r * SP);
                    float4 q0 = row4[0], q1 = row4[1], q2 = row4[2], q3 = row4[3];
                    unsigned long long pv[16];
                    pv[0]  = pack2(q0.x); pv[1]  = pack2(q0.y);
                    pv[2]  = pack2(q0.z); pv[3]  = pack2(q0.w);
                    pv[4]  = pack2(q1.x); pv[5]  = pack2(q1.y);
                    pv[6]  = pack2(q1.z); pv[7]  = pack2(q1.w);
                    pv[8]  = pack2(q2.x); pv[9]  = pack2(q2.y);
                    pv[10] = pack2(q2.z); pv[11] = pack2(q2.w);
                    pv[12] = pack2(q3.x); pv[13] = pack2(q3.y);
                    pv[14] = pack2(q3.z); pv[15] = pack2(q3.w);
                    #pragma unroll
                    for (int kw = 0; kw < 3; kw++) {
                        unsigned long long wk =
                            *reinterpret_cast<const unsigned long long*>(
                                w_base + (kh * 3 + kw) * CO_CHUNK);
                        #pragma unroll
                        for (int w = 0; w < WV; w++)
                            fma2(acc[w], pv[w + kw], wk);
                    }
                }
            }
        }

        // BN (eval) + ReLU epilogue, write padded rows (cols 0 and 15 = 0)
        const int co = co0 + 2 * cp;
        float sc0 = gam[co]     * rsqrtf(var[co]     + 1e-5f);
        float sc1 = gam[co + 1] * rsqrtf(var[co + 1] + 1e-5f);
        float sh0 = bet[co]     - mu[co]     * sc0;
        float sh1 = bet[co + 1] - mu[co + 1] * sc1;

        float* o0 = out + (size_t)b * (COUT * HOUT * WP)
                        + (size_t)co * (HOUT * WP) + h * WP;
        float* o1 = o0 + HOUT * WP;
        o0[0] = 0.f; o0[WV + 1] = 0.f;
        o1[0] = 0.f; o1[WV + 1] = 0.f;
        #pragma unroll
        for (int w = 0; w < WV; w++) {
            float2 a = unpack2(acc[w]);
            o0[w + 1] = fmaxf(fmaf(a.x, sc0, sh0), 0.f);
            o1[w + 1] = fmaxf(fmaf(a.y, sc1, sh1), 0.f);
        }
    }
}

// =====================================================================
// conv4: temporal merge (8,1) kernel, stride 1, no pad.
// out[b][w][co] = sum_{ci<256, kh<8} in[b][ci][kh][w] * w4[co][ci][kh]
// One warp per sample; lanes split ci; shuffle reduce.
// =====================================================================
__global__ void __launch_bounds__(256)
conv4_kernel(const float* __restrict__ in,   // [B][256][8][WP]
             const float* __restrict__ w4,   // [2][256][8][1]
             float* __restrict__ out)        // [B][14][2]
{
    const int warp = threadIdx.x >> 5;
    const int lane = threadIdx.x & 31;
    const int b = blockIdx.x * 8 + warp;

    const float* base = in + (size_t)b * 32768;
    float acc0[WV], acc1[WV];
    #pragma unroll
    for (int w = 0; w < WV; w++) { acc0[w] = 0.f; acc1[w] = 0.f; }

    for (int ci = lane; ci < 256; ci += 32) {
        const float* prow  = base + ci * (8 * WP);
        const float* wrow0 = w4 + ci * 8;
        const float* wrow1 = w4 + 2048 + ci * 8;
        #pragma unroll
        for (int kh = 0; kh < 8; kh++) {
            float w0 = wrow0[kh], w1 = wrow1[kh];
            const float4* r4 = reinterpret_cast<const float4*>(prow + kh * WP);
            float4 q0 = r4[0], q1 = r4[1], q2 = r4[2], q3 = r4[3];
            float v[16] = {q0.x,q0.y,q0.z,q0.w, q1.x,q1.y,q1.z,q1.w,
                           q2.x,q2.y,q2.z,q2.w, q3.x,q3.y,q3.z,q3.w};
            #pragma unroll
            for (int w = 0; w < WV; w++) {
                acc0[w] = fmaf(v[w + 1], w0, acc0[w]);
                acc1[w] = fmaf(v[w + 1], w1, acc1[w]);
            }
        }
    }
    #pragma unroll
    for (int off = 16; off > 0; off >>= 1) {
        #pragma unroll
        for (int w = 0; w < WV; w++) {
            acc0[w] += __shfl_down_sync(0xffffffffu, acc0[w], off);
            acc1[w] += __shfl_down_sync(0xffffffffu, acc1[w], off);
        }
    }
    if (lane == 0) {
        float* o = out + (size_t)b * (WV * 2);
        #pragma unroll
        for (int w = 0; w < WV; w++) {
            o[w * 2]     = acc0[w];
            o[w * 2 + 1] = acc1[w];
        }
    }
}

extern "C" void kernel_launch(void* const* d_in, const int* in_sizes, int n_in,
                              void* d_out, int out_size)
{
    (void)n_in; (void)out_size;
    const float* x   = (const float*)d_in[0];
    const float* sig = (const float*)d_in[1];
    const float* w1  = (const float*)d_in[2];
    const float *w2, *w3, *w4;
    const float *g1,*b1,*m1,*v1,*g2,*b2,*m2,*v2,*g3,*b3,*m3,*v3;

    if (in_sizes[3] == 73728) {
        // dict order: x, sigmas, w1, w2, w3, w4, g1,b1,m1,v1, g2,..., g3,...
        w2=(const float*)d_in[3];  w3=(const float*)d_in[4];  w4=(const float*)d_in[5];
        g1=(const float*)d_in[6];  b1=(const float*)d_in[7];  m1=(const float*)d_in[8];  v1=(const float*)d_in[9];
        g2=(const float*)d_in[10]; b2=(const float*)d_in[11]; m2=(const float*)d_in[12]; v2=(const float*)d_in[13];
        g3=(const float*)d_in[14]; b3=(const float*)d_in[15]; m3=(const float*)d_in[16]; v3=(const float*)d_in[17];
    } else {
        // reference-signature order: x, sigmas, w1, g1,b1,m1,v1, w2, g2,..., w3, g3,..., w4
        g1=(const float*)d_in[3];  b1=(const float*)d_in[4];  m1=(const float*)d_in[5];  v1=(const float*)d_in[6];
        w2=(const float*)d_in[7];
        g2=(const float*)d_in[8];  b2=(const float*)d_in[9];  m2=(const float*)d_in[10]; v2=(const float*)d_in[11];
        w3=(const float*)d_in[12];
        g3=(const float*)d_in[13]; b3=(const float*)d_in[14]; m3=(const float*)d_in[15]; v3=(const float*)d_in[16];
        w4=(const float*)d_in[17];
    }

    float *bufA = nullptr, *bufB = nullptr;
    cudaGetSymbolAddress((void**)&bufA, g_bufA);
    cudaGetSymbolAddress((void**)&bufB, g_bufB);

    const int smem1 = (2  * 64 * SP + 2  * 9 * 16) * 4;   //  ~11.4 KB
    const int smem2 = (64 * 32 * SP + 16 * 9 * 32) * 4;   // ~182 KB
    const int smem3 = (128* 16 * SP + 16 * 9 * 64) * 4;   // ~201 KB

    cudaFuncSetAttribute(conv_bn_relu_kernel<64,128,32,16,32,16,false>,
                         cudaFuncAttributeMaxDynamicSharedMemorySize, smem2);
    cudaFuncSetAttribute(conv_bn_relu_kernel<128,256,16,8,64,16,false>,
                         cudaFuncAttributeMaxDynamicSharedMemorySize, smem3);

    // conv1: [B,2,64,14] -> [B,64,32,14]
    conv_bn_relu_kernel<2,64,64,32,16,2,true><<<B_TOTAL, 256, smem1>>>(
        x, sig, w1, g1, b1, m1, v1, bufA);
    // conv2: -> [B,128,16,14]
    conv_bn_relu_kernel<64,128,32,16,32,16,false><<<B_TOTAL, 256, smem2>>>(
        bufA, nullptr, w2, g2, b2, m2, v2, bufB);
    // conv3: -> [B,256,8,14]
    conv_bn_relu_kernel<128,256,16,8,64,16,false><<<B_TOTAL, 256, smem3>>>(
        bufB, nullptr, w3, g3, b3, m3, v3, bufA);
    // conv4 + transpose: -> [B,14,2]
    conv4_kernel<<<B_TOTAL / 8, 256>>>(bufA, w4, (float*)d_out);
}

// round 2
// speedup vs baseline: 1.6202x; 1.6202x over previous
#include <cuda_runtime.h>
#include <cstdint>

#define WV 14          // valid width
#define WP 16          // padded width in global buffers (col 0 and 15 are zero pad)
#define SP 20          // smem row pitch (floats) - breaks bank conflicts
#define B_TOTAL 2048

// Scratch: per-sample slab is 32768 floats for every intermediate layer:
// conv1 out: 64*32*16, conv2 out: 128*16*16, conv3 out: 256*8*16  (all = 32768)
__device__ float g_bufA[(size_t)B_TOTAL * 32768];
__device__ float g_bufB[(size_t)B_TOTAL * 32768];
// Transposed weights [ci*9+k][co]: w1T @0 (1152), w2T @4096 (73728), w3T @81920 (294912)
__device__ float g_wT[4096 + 73728 + 294912 + 1024];

typedef unsigned long long ull;

// ---- packed f32x2 helpers (Blackwell sm_103a FFMA2 path) ----
__device__ __forceinline__ ull pack2(float x) {
    ull r;
    asm("mov.b64 %0, {%1, %1};" : "=l"(r) : "f"(x));
    return r;
}
__device__ __forceinline__ void fma2(ull &acc, ull a, ull b) {
    asm("fma.rn.f32x2 %0, %1, %2, %0;" : "+l"(acc) : "l"(a), "l"(b));
}
__device__ __forceinline__ float2 unpack2(ull v) {
    float2 r;
    asm("mov.b64 {%0, %1}, %2;" : "=f"(r.x), "=f"(r.y) : "l"(v));
    return r;
}

// =====================================================================
// Weight transpose: w[co][ci][3][3] -> wT[ci*9+k][co]  (coalesced reads)
// =====================================================================
__global__ void transpose_w_kernel(const float* __restrict__ w,
                                   float* __restrict__ wT,
                                   int CIN, int COUT)
{
    int i = blockIdx.x * 256 + threadIdx.x;
    int total = COUT * CIN * 9;
    if (i >= total) return;
    int co = i / (CIN * 9);
    int r  = i % (CIN * 9);     // ci*9 + k
    wT[r * COUT + co] = w[i];
}

// =====================================================================
// Fused conv(3x3, stride (2,1), pad (1,1)) + BN(eval) + ReLU.  512 thr.
// One CTA per batch sample; whole input slab in SMEM; ALL output
// channels accumulated in registers (2 co-pairs per thread).
// Thread (cp, h): co_a = 2*cp, co_b = COUT/2 + 2*cp.
// Requires HOUT * (COUT/4) == 512.
// =====================================================================
template<int CIN, int COUT, int HIN, int HOUT, int CI_BLK, bool FIRST>
__global__ void __launch_bounds__(512, 1)
conv_bn_relu_v2(const float* __restrict__ in0,
                const float* __restrict__ in1,    // sigmas when FIRST
                const float* __restrict__ wT,     // [CIN*9][COUT]
                const float* __restrict__ gam,
                const float* __restrict__ bet,
                const float* __restrict__ mu,
                const float* __restrict__ var,
                float* __restrict__ out)          // [B][COUT][HOUT][WP]
{
    constexpr int IN_G    = CIN * HIN * WP;
    constexpr int IN_SM   = CIN * HIN * SP;
    constexpr int W_ELEMS = CI_BLK * 9 * COUT;

    extern __shared__ float smem[];
    float* s_in = smem;                 // [CIN][HIN][SP]
    float* s_w  = smem + IN_SM;         // [CI_BLK][9][COUT]

    const int b   = blockIdx.x;
    const int tid = threadIdx.x;

    if (FIRST) {
        for (int r = tid; r < 2 * HIN; r += 512) {
            s_in[r * SP]          = 0.0f;
            s_in[r * SP + WV + 1] = 0.0f;
        }
        for (int i = tid; i < HIN * WV; i += 512) {
            int f = i / WV, k = i % WV;
            s_in[f * SP + 1 + k]         = in0[(size_t)b * (HIN * WV) + i];
            s_in[(HIN + f) * SP + 1 + k] = in1[(size_t)b * (HIN * WV) + i] * 10.0f;
        }
    } else {
        const float* gin = in0 + (size_t)b * IN_G;
        for (int i = tid * 4; i < IN_G; i += 512 * 4) {
            float4 v = *reinterpret_cast<const float4*>(gin + i);
            int row = i >> 4;       // / WP
            int col = i & 15;
            *reinterpret_cast<float4*>(s_in + row * SP + col) = v;
        }
    }

    const int h    = tid % HOUT;
    const int cp   = tid / HOUT;
    const int co_a = 2 * cp;
    const int co_b = COUT / 2 + 2 * cp;

    ull accA[WV], accB[WV];
    #pragma unroll
    for (int w = 0; w < WV; w++) { accA[w] = 0ull; accB[w] = 0ull; }

    for (int ci0 = 0; ci0 < CIN; ci0 += CI_BLK) {
        __syncthreads();            // protect s_w reuse + (first iter) s_in staging
        {   // coalesced float4 weight staging from pre-transposed layout
            const float4* src =
                reinterpret_cast<const float4*>(wT + (size_t)ci0 * 9 * COUT);
            float4* dst = reinterpret_cast<float4*>(s_w);
            for (int e = tid; e < W_ELEMS / 4; e += 512) dst[e] = src[e];
        }
        __syncthreads();

        for (int ci = 0; ci < CI_BLK; ci++) {
            const float* w_base = s_w + ci * 9 * COUT;
            const float* i_base = s_in + (ci0 + ci) * (HIN * SP);
            #pragma unroll
            for (int kh = 0; kh < 3; kh++) {
                int r = 2 * h - 1 + kh;
                if (r < 0) continue;           // only h==0, kh==0
                const float4* row4 = reinterpret_cast<const float4*>(i_base + r * SP);
                float4 q0 = row4[0], q1 = row4[1], q2 = row4[2], q3 = row4[3];
                ull pv[16];
                pv[0]  = pack2(q0.x); pv[1]  = pack2(q0.y);
                pv[2]  = pack2(q0.z); pv[3]  = pack2(q0.w);
                pv[4]  = pack2(q1.x); pv[5]  = pack2(q1.y);
                pv[6]  = pack2(q1.z); pv[7]  = pack2(q1.w);
                pv[8]  = pack2(q2.x); pv[9]  = pack2(q2.y);
                pv[10] = pack2(q2.z); pv[11] = pack2(q2.w);
                pv[12] = pack2(q3.x); pv[13] = pack2(q3.y);
                pv[14] = pack2(q3.z); pv[15] = pack2(q3.w);
                #pragma unroll
                for (int kw = 0; kw < 3; kw++) {
                    const float* wp = w_base + (kh * 3 + kw) * COUT;
                    ull wa = *reinterpret_cast<const ull*>(wp + co_a);
                    ull wb = *reinterpret_cast<const ull*>(wp + co_b);
                    #pragma unroll
                    for (int w = 0; w < WV; w++) {
                        fma2(accA[w], pv[w + kw], wa);
                        fma2(accB[w], pv[w + kw], wb);
                    }
                }
            }
        }
    }

    // BN (eval) + ReLU epilogue for both co-pairs
    float* obase = out + (size_t)b * (COUT * HOUT * WP);
    {
        float sc0 = gam[co_a]     * rsqrtf(var[co_a]     + 1e-5f);
        float sc1 = gam[co_a + 1] * rsqrtf(var[co_a + 1] + 1e-5f);
        float sh0 = bet[co_a]     - mu[co_a]     * sc0;
        float sh1 = bet[co_a + 1] - mu[co_a + 1] * sc1;
        float* o0 = obase + (size_t)co_a * (HOUT * WP) + h * WP;
        float* o1 = o0 + HOUT * WP;
        o0[0] = 0.f; o0[WV + 1] = 0.f;
        o1[0] = 0.f; o1[WV + 1] = 0.f;
        #pragma unroll
        for (int w = 0; w < WV; w++) {
            float2 a = unpack2(accA[w]);
            o0[w + 1] = fmaxf(fmaf(a.x, sc0, sh0), 0.f);
            o1[w + 1] = fmaxf(fmaf(a.y, sc1, sh1), 0.f);
        }
    }
    {
        float sc0 = gam[co_b]     * rsqrtf(var[co_b]     + 1e-5f);
        float sc1 = gam[co_b + 1] * rsqrtf(var[co_b + 1] + 1e-5f);
        float sh0 = bet[co_b]     - mu[co_b]     * sc0;
        float sh1 = bet[co_b + 1] - mu[co_b + 1] * sc1;
        float* o0 = obase + (size_t)co_b * (HOUT * WP) + h * WP;
        float* o1 = o0 + HOUT * WP;
        o0[0] = 0.f; o0[WV + 1] = 0.f;
        o1[0] = 0.f; o1[WV + 1] = 0.f;
        #pragma unroll
        for (int w = 0; w < WV; w++) {
            float2 a = unpack2(accB[w]);
            o0[w + 1] = fmaxf(fmaf(a.x, sc0, sh0), 0.f);
            o1[w + 1] = fmaxf(fmaf(a.y, sc1, sh1), 0.f);
        }
    }
}

// =====================================================================
// conv4: temporal merge (8,1), stride 1, no pad, fused transpose.
// 2 warps per sample (each handles 128 ci), smem combine.
// out[b][w][co] = sum_{ci<256,kh<8} in[b][ci][kh][w] * w4[co][ci][kh]
// =====================================================================
__global__ void __launch_bounds__(256)
conv4_kernel_v2(const float* __restrict__ in,   // [B][256][8][WP]
                const float* __restrict__ w4,   // [2][256][8][1]
                float* __restrict__ out)        // [B][14][2]
{
    __shared__ float part[8][28];
    const int warp = threadIdx.x >> 5;
    const int lane = threadIdx.x & 31;
    const int b    = blockIdx.x * 4 + (warp >> 1);
    const int half = warp & 1;

    const float* base = in + (size_t)b * 32768;
    float acc0[WV], acc1[WV];
    #pragma unroll
    for (int w = 0; w < WV; w++) { acc0[w] = 0.f; acc1[w] = 0.f; }

    const int ci_lo = 128 * half;
    for (int ci = ci_lo + lane; ci < ci_lo + 128; ci += 32) {
        const float* prow  = base + ci * (8 * WP);
        const float* wrow0 = w4 + ci * 8;
        const float* wrow1 = w4 + 2048 + ci * 8;
        #pragma unroll
        for (int kh = 0; kh < 8; kh++) {
            float w0 = wrow0[kh], w1 = wrow1[kh];
            const float4* r4 = reinterpret_cast<const float4*>(prow + kh * WP);
            float4 q0 = r4[0], q1 = r4[1], q2 = r4[2], q3 = r4[3];
            float v[16] = {q0.x,q0.y,q0.z,q0.w, q1.x,q1.y,q1.z,q1.w,
                           q2.x,q2.y,q2.z,q2.w, q3.x,q3.y,q3.z,q3.w};
            #pragma unroll
            for (int w = 0; w < WV; w++) {
                acc0[w] = fmaf(v[w + 1], w0, acc0[w]);
                acc1[w] = fmaf(v[w + 1], w1, acc1[w]);
            }
        }
    }
    #pragma unroll
    for (int off = 16; off > 0; off >>= 1) {
        #pragma unroll
        for (int w = 0; w < WV; w++) {
            acc0[w] += __shfl_down_sync(0xffffffffu, acc0[w], off);
            acc1[w] += __shfl_down_sync(0xffffffffu, acc1[w], off);
        }
    }
    if (lane == 0) {
        #pragma unroll
        for (int w = 0; w < WV; w++) {
            part[warp][w]      = acc0[w];
            part[warp][14 + w] = acc1[w];
        }
    }
    __syncthreads();
    if (threadIdx.x < 112) {
        int s = threadIdx.x / 28, j = threadIdx.x % 28;
        float v = part[2 * s][j] + part[2 * s + 1][j];
        int bb = blockIdx.x * 4 + s;
        int c = j / 14, w = j % 14;
        out[(size_t)bb * 28 + w * 2 + c] = v;
    }
}

extern "C" void kernel_launch(void* const* d_in, const int* in_sizes, int n_in,
                              void* d_out, int out_size)
{
    (void)n_in; (void)out_size;
    const float* x   = (const float*)d_in[0];
    const float* sig = (const float*)d_in[1];
    const float* w1  = (const float*)d_in[2];
    const float *w2, *w3, *w4;
    const float *g1,*b1,*m1,*v1,*g2,*b2,*m2,*v2,*g3,*b3,*m3,*v3;

    if (in_sizes[3] == 73728) {
        // dict order: x, sigmas, w1, w2, w3, w4, g1,b1,m1,v1, g2,..., g3,...
        w2=(const float*)d_in[3];  w3=(const float*)d_in[4];  w4=(const float*)d_in[5];
        g1=(const float*)d_in[6];  b1=(const float*)d_in[7];  m1=(const float*)d_in[8];  v1=(const float*)d_in[9];
        g2=(const float*)d_in[10]; b2=(const float*)d_in[11]; m2=(const float*)d_in[12]; v2=(const float*)d_in[13];
        g3=(const float*)d_in[14]; b3=(const float*)d_in[15]; m3=(const float*)d_in[16]; v3=(const float*)d_in[17];
    } else {
        // reference-signature order: x, sigmas, w1, g1,b1,m1,v1, w2, g2,..., w3, g3,..., w4
        g1=(const float*)d_in[3];  b1=(const float*)d_in[4];  m1=(const float*)d_in[5];  v1=(const float*)d_in[6];
        w2=(const float*)d_in[7];
        g2=(const float*)d_in[8];  b2=(const float*)d_in[9];  m2=(const float*)d_in[10]; v2=(const float*)d_in[11];
        w3=(const float*)d_in[12];
        g3=(const float*)d_in[13]; b3=(const float*)d_in[14]; m3=(const float*)d_in[15]; v3=(const float*)d_in[16];
        w4=(const float*)d_in[17];
    }

    float *bufA = nullptr, *bufB = nullptr, *wT = nullptr;
    cudaGetSymbolAddress((void**)&bufA, g_bufA);
    cudaGetSymbolAddress((void**)&bufB, g_bufB);
    cudaGetSymbolAddress((void**)&wT,   g_wT);
    float* w1T = wT;
    float* w2T = wT + 4096;
    float* w3T = wT + 81920;

    // Pre-transpose weights to [ci*9+k][co]
    transpose_w_kernel<<<(64 * 2 * 9 + 255) / 256, 256>>>(w1, w1T, 2, 64);
    transpose_w_kernel<<<(128 * 64 * 9 + 255) / 256, 256>>>(w2, w2T, 64, 128);
    transpose_w_kernel<<<(256 * 128 * 9 + 255) / 256, 256>>>(w3, w3T, 128, 256);

    const int smem1 = (2   * 64 * SP + 2 * 9 * 64)  * 4;   // ~14.5 KB
    const int smem2 = (64  * 32 * SP + 8 * 9 * 128) * 4;   // ~196 KB
    const int smem3 = (128 * 16 * SP + 4 * 9 * 256) * 4;   // ~196 KB

    cudaFuncSetAttribute(conv_bn_relu_v2<64,128,32,16,8,false>,
                         cudaFuncAttributeMaxDynamicSharedMemorySize, smem2);
    cudaFuncSetAttribute(conv_bn_relu_v2<128,256,16,8,4,false>,
                         cudaFuncAttributeMaxDynamicSharedMemorySize, smem3);

    // conv1: [B,2,64,14] -> [B,64,32,14]
    conv_bn_relu_v2<2,64,64,32,2,true><<<B_TOTAL, 512, smem1>>>(
        x, sig, w1T, g1, b1, m1, v1, bufA);
    // conv2: -> [B,128,16,14]
    conv_bn_relu_v2<64,128,32,16,8,false><<<B_TOTAL, 512, smem2>>>(
        bufA, nullptr, w2T, g2, b2, m2, v2, bufB);
    // conv3: -> [B,256,8,14]
    conv_bn_relu_v2<128,256,16,8,4,false><<<B_TOTAL, 512, smem3>>>(
        bufB, nullptr, w3T, g3, b3, m3, v3, bufA);
    // conv4 + transpose: -> [B,14,2]
    conv4_kernel_v2<<<B_TOTAL / 4, 256>>>(bufA, w4, (float*)d_out);
}